// round 5
// baseline (speedup 1.0000x reference)
#include <cuda_runtime.h>

#define N_RES 2048
#define BATCH 16
#define LMAXP 13
#define NTYPES 20
#define MAXROWS 28672
#define ROWS_PER_BLK 8

__constant__ int c_reslen[NTYPES] = {3, 4, 5, 5, 6, 6, 6, 7, 7, 7, 7, 7, 8, 8, 8, 9, 10, 10, 11, 13};

// Per-row descriptor: {type, m (-1 for amn row), residue, start}
__device__ int4 g_rowdesc[MAXROWS];

// ---------------------------------------------------------------------------
// Kernel 1: prefix-scan of residue lengths + build row descriptors.
// 1 block, 1024 threads, each handles residues 2t, 2t+1.
// ---------------------------------------------------------------------------
__global__ void scan_fill_kernel(const int* __restrict__ seq, int atoms) {
    int t = threadIdx.x;  // 0..1023
    int s0 = seq[2 * t];
    int s1 = seq[2 * t + 1];
    int l0 = c_reslen[s0];
    int l1 = c_reslen[s1];
    int a = l0 + l1;

    // warp-inclusive scan
    int v = a;
#pragma unroll
    for (int off = 1; off < 32; off <<= 1) {
        int n = __shfl_up_sync(0xFFFFFFFFu, v, off);
        if ((t & 31) >= off) v += n;
    }

    __shared__ int wsum[32];
    if ((t & 31) == 31) wsum[t >> 5] = v;
    __syncthreads();
    if (t < 32) {
        int s = wsum[t];
        int x = s;
#pragma unroll
        for (int off = 1; off < 32; off <<= 1) {
            int n = __shfl_up_sync(0xFFFFFFFFu, x, off);
            if (t >= off) x += n;
        }
        wsum[t] = x - s;  // exclusive warp offset
    }
    __syncthreads();

    int excl = wsum[t >> 5] + (v - a);
    int start0 = excl;
    int start1 = excl + l0;

    for (int l = 0; l < l0; l++) g_rowdesc[start0 + l] = make_int4(s0, l, 2 * t, start0);
    for (int l = 0; l < l1; l++) g_rowdesc[start1 + l] = make_int4(s1, l, 2 * t + 1, start1);
    g_rowdesc[atoms + 2 * t]     = make_int4(s0, -1, 2 * t, start0);
    g_rowdesc[atoms + 2 * t + 1] = make_int4(s1, -1, 2 * t + 1, start1);
}

// ---------------------------------------------------------------------------
// Per-row compute: one warp, 2 v-rows per thread (v=lane, lane+32).
// Plain FFMA version (no f32x2 asm).
// ---------------------------------------------------------------------------
template <int L>
__device__ __forceinline__ void row_compute(
    const float4* __restrict__ sd,     // [BATCH][LMAXP] diffs, .w=0
    const float* __restrict__ wr0,
    const float* __restrict__ wr1,
    float* __restrict__ obase, size_t ostride, int lane)
{
    float w0[L], w1[L];
#pragma unroll
    for (int l = 0; l < L; l++) {
        w0[l] = wr0[l];
        w1[l] = wr1[l];
    }

#pragma unroll 1
    for (int b = 0; b < BATCH; b++) {
        const float4* d = sd + b * LMAXP;
        float x0 = 0.f, y0 = 0.f, z0 = 0.f;
        float x1 = 0.f, y1 = 0.f, z1 = 0.f;
#pragma unroll
        for (int l = 0; l < L; l++) {
            float4 v4 = d[l];
            x0 = fmaf(w0[l], v4.x, x0);
            y0 = fmaf(w0[l], v4.y, y0);
            z0 = fmaf(w0[l], v4.z, z0);
            x1 = fmaf(w1[l], v4.x, x1);
            y1 = fmaf(w1[l], v4.y, y1);
            z1 = fmaf(w1[l], v4.z, z1);
        }
        float* o = obase + (size_t)b * ostride;
        int e0 = 3 * lane;
        int e1 = 3 * (lane + 32);
        o[e0] = x0; o[e0 + 1] = y0; o[e0 + 2] = z0;
        o[e1] = x1; o[e1 + 1] = y1; o[e1 + 2] = z1;
    }
}

// ---------------------------------------------------------------------------
// Main kernel: one warp per output row (atom rows first, then amn rows).
// Block = 8 warps; diffs staged once per unique residue in the block.
// ---------------------------------------------------------------------------
__global__ void __launch_bounds__(256, 3) posmix_main(
    const float* __restrict__ pos_atm,
    const float* __restrict__ pos_amn,
    const float* __restrict__ W_amn,
    const float* __restrict__ W_atm,
    float* __restrict__ out_atm,
    float* __restrict__ out_amn,
    int atoms, int nrows)
{
    __shared__ float4 sdiff[ROWS_PER_BLK][BATCH][LMAXP];
    __shared__ int s_res[ROWS_PER_BLK];

    const int tid = threadIdx.x;
    const int warp = tid >> 5;
    const int lane = tid & 31;
    const int row = blockIdx.x * ROWS_PER_BLK + warp;
    const bool active = row < nrows;

    int4 dsc = make_int4(0, -1, -1 - warp, 0);
    if (active) dsc = g_rowdesc[row];
    const int t = dsc.x;
    const int m = dsc.y;
    const int ri = dsc.z;
    const int start = dsc.w;
    const int L = active ? c_reslen[t] : 0;

    if (lane == 0) s_res[warp] = ri;
    __syncthreads();

    // First warp in block with the same residue owns the diff slab.
    int slab = warp;
#pragma unroll
    for (int g = 0; g < ROWS_PER_BLK; g++) {
        if (g < warp && s_res[g] == ri && slab == warp) slab = g;
    }
    const bool owner = active && (slab == warp);

    if (owner) {
        for (int idx = lane; idx < BATCH * L; idx += 32) {
            int b = idx / L;
            int l = idx - b * L;
            const float* pa = pos_atm + ((size_t)b * atoms + (start + l)) * 3;
            const float* pm = pos_amn + ((size_t)b * N_RES + ri) * 3;
            sdiff[warp][b][l] = make_float4(pa[0] - pm[0], pa[1] - pm[1], pa[2] - pm[2], 0.f);
        }
    }
    __syncthreads();

    if (!active) return;

    const float4* sd = &sdiff[slab][0][0];
    const float* wr0;
    float* obase;
    size_t ostride;
    if (m >= 0) {
        wr0 = W_atm + (((size_t)t * LMAXP + m) * 64 + lane) * LMAXP;
        obase = out_atm + (size_t)row * 192;
        ostride = (size_t)atoms * 192;
    } else {
        wr0 = W_amn + ((size_t)t * 64 + lane) * LMAXP;
        obase = out_amn + (size_t)ri * 192;
        ostride = (size_t)N_RES * 192;
    }
    const float* wr1 = wr0 + 32 * LMAXP;

    switch (L) {
        case 3:  row_compute<3 >(sd, wr0, wr1, obase, ostride, lane); break;
        case 4:  row_compute<4 >(sd, wr0, wr1, obase, ostride, lane); break;
        case 5:  row_compute<5 >(sd, wr0, wr1, obase, ostride, lane); break;
        case 6:  row_compute<6 >(sd, wr0, wr1, obase, ostride, lane); break;
        case 7:  row_compute<7 >(sd, wr0, wr1, obase, ostride, lane); break;
        case 8:  row_compute<8 >(sd, wr0, wr1, obase, ostride, lane); break;
        case 9:  row_compute<9 >(sd, wr0, wr1, obase, ostride, lane); break;
        case 10: row_compute<10>(sd, wr0, wr1, obase, ostride, lane); break;
        case 11: row_compute<11>(sd, wr0, wr1, obase, ostride, lane); break;
        case 13: row_compute<13>(sd, wr0, wr1, obase, ostride, lane); break;
        default: break;
    }
}

// ---------------------------------------------------------------------------
// Launch
// in: 0 pos_atm (B, atoms, 3) f32
//     1 pos_amn (B, 2048, 3) f32
//     2 W_amn   (20, 64, 13) f32
//     3 W_atm   (20, 13, 64, 13) f32
//     4 seq_types (2048,) i32
// out: [x_v_atm (B, atoms, 64, 3) | x_v_amn (B, 2048, 64, 3)] f32
// ---------------------------------------------------------------------------
extern "C" void kernel_launch(void* const* d_in, const int* in_sizes, int n_in,
                              void* d_out, int out_size)
{
    const float* pos_atm = (const float*)d_in[0];
    const float* pos_amn = (const float*)d_in[1];
    const float* W_amn   = (const float*)d_in[2];
    const float* W_atm   = (const float*)d_in[3];
    const int*   seq     = (const int*)d_in[4];

    const int atoms = in_sizes[0] / (BATCH * 3);
    const int nrows = atoms + N_RES;

    float* out_atm = (float*)d_out;
    float* out_amn = out_atm + (size_t)BATCH * atoms * 64 * 3;

    scan_fill_kernel<<<1, 1024>>>(seq, atoms);

    int grid = (nrows + ROWS_PER_BLK - 1) / ROWS_PER_BLK;
    posmix_main<<<grid, 256>>>(pos_atm, pos_amn, W_amn, W_atm,
                               out_atm, out_amn, atoms, nrows);
}

// round 6
// speedup vs baseline: 1.1770x; 1.1770x over previous
#include <cuda_runtime.h>

#define N_RES 2048
#define BATCH 16
#define LMAXP 13
#define NTYPES 20
#define MAXROWS 28672
#define ROWS_PER_BLK 8

#define WATM_T_ELEMS (NTYPES * LMAXP * LMAXP * 64)   // 216320
#define WAMN_T_ELEMS (NTYPES * LMAXP * 64)           // 16640

__constant__ int c_reslen[NTYPES] = {3, 4, 5, 5, 6, 6, 6, 7, 7, 7, 7, 7, 8, 8, 8, 9, 10, 10, 11, 13};

__device__ int g_starts[N_RES];
// Per-row descriptor: {type, m (-1 for amn row), residue, start}
__device__ int4 g_rowdesc[MAXROWS];
// Pre-transposed weights: WatmT[t][m][l][v], WamnT[t][l][o]
__device__ float g_WatmT[WATM_T_ELEMS];
__device__ float g_WamnT[WAMN_T_ELEMS];

// ---------------------------------------------------------------------------
// Kernel A: exclusive prefix-sum of residue lengths -> g_starts (1 block).
// ---------------------------------------------------------------------------
__global__ void scan_kernel(const int* __restrict__ seq) {
    int t = threadIdx.x;  // 0..1023
    int l0 = c_reslen[seq[2 * t]];
    int l1 = c_reslen[seq[2 * t + 1]];
    int a = l0 + l1;

    int v = a;
#pragma unroll
    for (int off = 1; off < 32; off <<= 1) {
        int n = __shfl_up_sync(0xFFFFFFFFu, v, off);
        if ((t & 31) >= off) v += n;
    }

    __shared__ int wsum[32];
    if ((t & 31) == 31) wsum[t >> 5] = v;
    __syncthreads();
    if (t < 32) {
        int s = wsum[t];
        int x = s;
#pragma unroll
        for (int off = 1; off < 32; off <<= 1) {
            int n = __shfl_up_sync(0xFFFFFFFFu, x, off);
            if (t >= off) x += n;
        }
        wsum[t] = x - s;
    }
    __syncthreads();

    int excl = wsum[t >> 5] + (v - a);
    g_starts[2 * t] = excl;
    g_starts[2 * t + 1] = excl + l0;
}

// ---------------------------------------------------------------------------
// Kernel B: parallel row-descriptor fill. One thread per residue.
// ---------------------------------------------------------------------------
__global__ void fill_kernel(const int* __restrict__ seq, int atoms) {
    int i = blockIdx.x * blockDim.x + threadIdx.x;
    if (i >= N_RES) return;
    int t = seq[i];
    int L = c_reslen[t];
    int start = g_starts[i];
    for (int l = 0; l < L; l++) g_rowdesc[start + l] = make_int4(t, l, i, start);
    g_rowdesc[atoms + i] = make_int4(t, -1, i, start);
}

// ---------------------------------------------------------------------------
// Kernel C: transpose weights for coalesced per-lane access.
//   g_WatmT[((t*13+m)*13+l)*64 + v] = W_atm[((t*13+m)*64+v)*13 + l]
//   g_WamnT[(t*13+l)*64 + o]        = W_amn[(t*64+o)*13 + l]
// ---------------------------------------------------------------------------
__global__ void transpose_w_kernel(const float* __restrict__ W_amn,
                                   const float* __restrict__ W_atm) {
    int idx = blockIdx.x * blockDim.x + threadIdx.x;
    if (idx < WATM_T_ELEMS) {
        int v = idx & 63;
        int r = idx >> 6;
        int l = r % LMAXP; r /= LMAXP;
        int m = r % LMAXP;
        int t = r / LMAXP;
        g_WatmT[idx] = W_atm[((size_t)(t * LMAXP + m) * 64 + v) * LMAXP + l];
    } else {
        int j = idx - WATM_T_ELEMS;
        if (j < WAMN_T_ELEMS) {
            int o = j & 63;
            int r = j >> 6;
            int l = r % LMAXP;
            int t = r / LMAXP;
            g_WamnT[j] = W_amn[((size_t)t * 64 + o) * LMAXP + l];
        }
    }
}

// ---------------------------------------------------------------------------
// Per-row compute: one warp, 2 v-rows per thread (v=lane, lane+32).
// Weights loaded coalesced from transposed tables.
// ---------------------------------------------------------------------------
template <int L>
__device__ __forceinline__ void row_compute(
    const float4* __restrict__ sd,     // [BATCH][LMAXP] diffs, .w=0
    const float* __restrict__ wt,      // transposed weight base + lane
    float* __restrict__ obase, size_t ostride, int lane)
{
    float w0[L], w1[L];
#pragma unroll
    for (int l = 0; l < L; l++) {
        w0[l] = wt[l * 64];
        w1[l] = wt[l * 64 + 32];
    }

#pragma unroll 1
    for (int b = 0; b < BATCH; b++) {
        const float4* d = sd + b * LMAXP;
        float x0 = 0.f, y0 = 0.f, z0 = 0.f;
        float x1 = 0.f, y1 = 0.f, z1 = 0.f;
#pragma unroll
        for (int l = 0; l < L; l++) {
            float4 v4 = d[l];
            x0 = fmaf(w0[l], v4.x, x0);
            y0 = fmaf(w0[l], v4.y, y0);
            z0 = fmaf(w0[l], v4.z, z0);
            x1 = fmaf(w1[l], v4.x, x1);
            y1 = fmaf(w1[l], v4.y, y1);
            z1 = fmaf(w1[l], v4.z, z1);
        }
        float* o = obase + (size_t)b * ostride;
        int e0 = 3 * lane;
        int e1 = 3 * (lane + 32);
        o[e0] = x0; o[e0 + 1] = y0; o[e0 + 2] = z0;
        o[e1] = x1; o[e1 + 1] = y1; o[e1 + 2] = z1;
    }
}

// ---------------------------------------------------------------------------
// Kernel D: main. One warp per output row; 8 warps/block; diff-slab dedupe.
// ---------------------------------------------------------------------------
__global__ void __launch_bounds__(256, 4) posmix_main(
    const float* __restrict__ pos_atm,
    const float* __restrict__ pos_amn,
    float* __restrict__ out_atm,
    float* __restrict__ out_amn,
    int atoms, int nrows)
{
    __shared__ float4 sdiff[ROWS_PER_BLK][BATCH][LMAXP];
    __shared__ int s_res[ROWS_PER_BLK];

    const int tid = threadIdx.x;
    const int warp = tid >> 5;
    const int lane = tid & 31;
    const int row = blockIdx.x * ROWS_PER_BLK + warp;
    const bool active = row < nrows;

    int4 dsc = make_int4(0, -1, -1 - warp, 0);
    if (active) dsc = g_rowdesc[row];
    const int t = dsc.x;
    const int m = dsc.y;
    const int ri = dsc.z;
    const int start = dsc.w;
    const int L = active ? c_reslen[t] : 0;

    if (lane == 0) s_res[warp] = ri;
    __syncthreads();

    // First warp in block with the same residue owns the diff slab.
    int slab = warp;
#pragma unroll
    for (int g = 0; g < ROWS_PER_BLK; g++) {
        if (g < warp && s_res[g] == ri && slab == warp) slab = g;
    }
    const bool owner = active && (slab == warp);

    if (owner) {
        for (int idx = lane; idx < BATCH * L; idx += 32) {
            int b = idx / L;
            int l = idx - b * L;
            const float* pa = pos_atm + ((size_t)b * atoms + (start + l)) * 3;
            const float* pm = pos_amn + ((size_t)b * N_RES + ri) * 3;
            sdiff[warp][b][l] = make_float4(pa[0] - pm[0], pa[1] - pm[1], pa[2] - pm[2], 0.f);
        }
    }
    __syncthreads();

    if (!active) return;

    const float4* sd = &sdiff[slab][0][0];
    const float* wt;
    float* obase;
    size_t ostride;
    if (m >= 0) {
        wt = g_WatmT + (size_t)((t * LMAXP + m) * LMAXP) * 64 + lane;
        obase = out_atm + (size_t)row * 192;
        ostride = (size_t)atoms * 192;
    } else {
        wt = g_WamnT + (size_t)(t * LMAXP) * 64 + lane;
        obase = out_amn + (size_t)ri * 192;
        ostride = (size_t)N_RES * 192;
    }

    switch (L) {
        case 3:  row_compute<3 >(sd, wt, obase, ostride, lane); break;
        case 4:  row_compute<4 >(sd, wt, obase, ostride, lane); break;
        case 5:  row_compute<5 >(sd, wt, obase, ostride, lane); break;
        case 6:  row_compute<6 >(sd, wt, obase, ostride, lane); break;
        case 7:  row_compute<7 >(sd, wt, obase, ostride, lane); break;
        case 8:  row_compute<8 >(sd, wt, obase, ostride, lane); break;
        case 9:  row_compute<9 >(sd, wt, obase, ostride, lane); break;
        case 10: row_compute<10>(sd, wt, obase, ostride, lane); break;
        case 11: row_compute<11>(sd, wt, obase, ostride, lane); break;
        case 13: row_compute<13>(sd, wt, obase, ostride, lane); break;
        default: break;
    }
}

// ---------------------------------------------------------------------------
// Launch
// in: 0 pos_atm (B, atoms, 3) f32
//     1 pos_amn (B, 2048, 3) f32
//     2 W_amn   (20, 64, 13) f32
//     3 W_atm   (20, 13, 64, 13) f32
//     4 seq_types (2048,) i32
// out: [x_v_atm (B, atoms, 64, 3) | x_v_amn (B, 2048, 64, 3)] f32
// ---------------------------------------------------------------------------
extern "C" void kernel_launch(void* const* d_in, const int* in_sizes, int n_in,
                              void* d_out, int out_size)
{
    const float* pos_atm = (const float*)d_in[0];
    const float* pos_amn = (const float*)d_in[1];
    const float* W_amn   = (const float*)d_in[2];
    const float* W_atm   = (const float*)d_in[3];
    const int*   seq     = (const int*)d_in[4];

    const int atoms = in_sizes[0] / (BATCH * 3);
    const int nrows = atoms + N_RES;

    float* out_atm = (float*)d_out;
    float* out_amn = out_atm + (size_t)BATCH * atoms * 64 * 3;

    scan_kernel<<<1, 1024>>>(seq);
    fill_kernel<<<(N_RES + 255) / 256, 256>>>(seq, atoms);

    int wgrid = (WATM_T_ELEMS + WAMN_T_ELEMS + 255) / 256;
    transpose_w_kernel<<<wgrid, 256>>>(W_amn, W_atm);

    int grid = (nrows + ROWS_PER_BLK - 1) / ROWS_PER_BLK;
    posmix_main<<<grid, 256>>>(pos_atm, pos_amn, out_atm, out_amn, atoms, nrows);
}